// round 1
// baseline (speedup 1.0000x reference)
#include <cuda_runtime.h>
#include <cstddef>

#define D_MODEL 2048
#define N_HEADS 16
#define D_HEAD  128
#define RANK    32
#define BATCH   2
#define SEQ     2048
#define M_TOT   (BATCH*SEQ)        // 4096
#define N_QKV   (3*N_HEADS*RANK)   // 1536
#define K_FOLD  (N_HEADS*RANK)     // 512

// ---------------- device scratch (no allocations allowed) ----------------
__device__ float g_Aqkv[(size_t)D_MODEL * N_QKV];          // [2048][1536]
__device__ float g_Bo[(size_t)K_FOLD * D_MODEL];           // [512][2048]
__device__ float g_qr[(size_t)BATCH * N_HEADS * SEQ * RANK];
__device__ float g_kr[(size_t)BATCH * N_HEADS * SEQ * RANK];
__device__ float g_vr[(size_t)BATCH * N_HEADS * SEQ * RANK];
__device__ float g_yr[(size_t)M_TOT * K_FOLD];             // [4096][512]

// ---------------- fold Wq/Wk/Wv with Wdown -------------------------------
// A_qkv[d][w*512 + h*32 + r] = sum_i W_w[h*128+i][d] * Wdown[i][r]
__global__ void fold_qkv(const float* __restrict__ Wq, const float* __restrict__ Wk,
                         const float* __restrict__ Wv, const float* __restrict__ Wdown) {
    __shared__ float sWd[D_HEAD][RANK];
    int tid = threadIdx.x;  // 128
    for (int i = tid; i < D_HEAD*RANK/4; i += 128)
        ((float4*)&sWd[0][0])[i] = ((const float4*)Wdown)[i];
    __syncthreads();

    int h = blockIdx.y;
    int w = blockIdx.z;
    int d = blockIdx.x * 128 + tid;
    const float* W = (w == 0) ? Wq : (w == 1) ? Wk : Wv;
    const float* wp = W + (size_t)h * D_HEAD * D_MODEL + d;

    float acc[RANK];
#pragma unroll
    for (int r = 0; r < RANK; r++) acc[r] = 0.f;
#pragma unroll 4
    for (int i = 0; i < D_HEAD; i++) {
        float wv = wp[(size_t)i * D_MODEL];
#pragma unroll
        for (int r = 0; r < RANK; r++) acc[r] += wv * sWd[i][r];
    }
    float* out = g_Aqkv + (size_t)d * N_QKV + w * K_FOLD + h * RANK;
#pragma unroll
    for (int r = 0; r < RANK; r += 4)
        *(float4*)(out + r) = make_float4(acc[r], acc[r+1], acc[r+2], acc[r+3]);
}

// ---------------- fold Wup with Wo ---------------------------------------
// B_o[h*32+r][j] = sum_i Wup[r][i] * Wo[j][h*128+i]
__global__ void fold_out(const float* __restrict__ Wo, const float* __restrict__ Wup) {
    __shared__ float sWup[RANK][D_HEAD];
    int tid = threadIdx.x;  // 128
    for (int i = tid; i < RANK*D_HEAD/4; i += 128)
        ((float4*)&sWup[0][0])[i] = ((const float4*)Wup)[i];
    __syncthreads();

    int h = blockIdx.y;
    int j = blockIdx.x * 128 + tid;
    const float* wop = Wo + (size_t)j * D_MODEL + h * D_HEAD;

    float acc[RANK];
#pragma unroll
    for (int r = 0; r < RANK; r++) acc[r] = 0.f;
#pragma unroll 2
    for (int i = 0; i < D_HEAD; i += 4) {
        float4 w4 = *(const float4*)(wop + i);
#pragma unroll
        for (int r = 0; r < RANK; r++)
            acc[r] += w4.x * sWup[r][i] + w4.y * sWup[r][i+1]
                    + w4.z * sWup[r][i+2] + w4.w * sWup[r][i+3];
    }
#pragma unroll
    for (int r = 0; r < RANK; r++)
        g_Bo[(size_t)(h * RANK + r) * D_MODEL + j] = acc[r];
}

// ---------------- generic 128x128 fp32 GEMM, double-buffered -------------
// C[M,N] = A[M,K] @ B[K,N]  (row-major). EPI=0: plain store. EPI=1: scatter
// into g_qr/g_kr/g_vr with layout [(b*16+h)*2048 + t]*32 + r.
template <int EPI>
__global__ __launch_bounds__(256)
void gemm_kernel(const float* __restrict__ A, const float* __restrict__ B,
                 float* __restrict__ C, int M, int N, int K) {
    __shared__ float As[2][8][128];
    __shared__ float Bs[2][8][128];
    int tid = threadIdx.x;
    int m0 = blockIdx.y * 128;
    int n0 = blockIdx.x * 128;

    int ar = tid >> 1;           // 0..127
    int ac = (tid & 1) * 4;      // 0 or 4
    int br = tid >> 5;           // 0..7
    int bc = (tid & 31) * 4;     // 0..124

    const float* Aptr = A + (size_t)(m0 + ar) * K + ac;
    const float* Bptr = B + (size_t)br * N + n0 + bc;

    // stage 0
    {
        float4 av = *(const float4*)Aptr;
        float4 bv = *(const float4*)Bptr;
        As[0][ac+0][ar] = av.x; As[0][ac+1][ar] = av.y;
        As[0][ac+2][ar] = av.z; As[0][ac+3][ar] = av.w;
        *(float4*)&Bs[0][br][bc] = bv;
    }
    __syncthreads();

    int ty = tid >> 4, tx = tid & 15;
    float acc[8][8];
#pragma unroll
    for (int i = 0; i < 8; i++)
#pragma unroll
        for (int j = 0; j < 8; j++) acc[i][j] = 0.f;

    int nkt = K >> 3;
    int buf = 0;
    for (int kt = 0; kt < nkt; kt++) {
        float4 an, bn;
        bool more = (kt + 1 < nkt);
        if (more) {
            an = *(const float4*)(Aptr + (kt + 1) * 8);
            bn = *(const float4*)(Bptr + (size_t)(kt + 1) * 8 * N);
        }
#pragma unroll
        for (int k = 0; k < 8; k++) {
            float a[8], b[8];
            *(float4*)(a)     = *(const float4*)&As[buf][k][ty * 8];
            *(float4*)(a + 4) = *(const float4*)&As[buf][k][ty * 8 + 4];
            *(float4*)(b)     = *(const float4*)&Bs[buf][k][tx * 8];
            *(float4*)(b + 4) = *(const float4*)&Bs[buf][k][tx * 8 + 4];
#pragma unroll
            for (int i = 0; i < 8; i++)
#pragma unroll
                for (int j = 0; j < 8; j++)
                    acc[i][j] += a[i] * b[j];
        }
        if (more) {
            int nb = buf ^ 1;
            As[nb][ac+0][ar] = an.x; As[nb][ac+1][ar] = an.y;
            As[nb][ac+2][ar] = an.z; As[nb][ac+3][ar] = an.w;
            *(float4*)&Bs[nb][br][bc] = bn;
        }
        __syncthreads();
        buf ^= 1;
    }

    if (EPI == 0) {
#pragma unroll
        for (int i = 0; i < 8; i++) {
            float* cp = C + (size_t)(m0 + ty * 8 + i) * N + n0 + tx * 8;
            *(float4*)(cp)     = make_float4(acc[i][0], acc[i][1], acc[i][2], acc[i][3]);
            *(float4*)(cp + 4) = make_float4(acc[i][4], acc[i][5], acc[i][6], acc[i][7]);
        }
    } else {
        int c0 = n0 + tx * 8;       // global column; 8 consecutive within one 32-block
        int w  = c0 >> 9;           // 0,1,2 -> q,k,v
        int hc = c0 & 511;
        int h  = hc >> 5;
        int r0 = hc & 31;
        float* base = (w == 0) ? g_qr : (w == 1) ? g_kr : g_vr;
#pragma unroll
        for (int i = 0; i < 8; i++) {
            int m = m0 + ty * 8 + i;
            int b = m >> 11, t = m & 2047;
            float* cp = base + ((size_t)(b * N_HEADS + h) * SEQ + t) * RANK + r0;
            *(float4*)(cp)     = make_float4(acc[i][0], acc[i][1], acc[i][2], acc[i][3]);
            *(float4*)(cp + 4) = make_float4(acc[i][4], acc[i][5], acc[i][6], acc[i][7]);
        }
    }
}

// ---------------- flash attention in rank space (d = 32) -----------------
// One thread per query row; K/V tiles staged in smem, read via warp-broadcast.
__global__ __launch_bounds__(128, 3)
void attn_kernel() {
    __shared__ float sK[64 * 32];
    __shared__ float sV[64 * 32];
    int tid = threadIdx.x;           // 0..127 -> query row within tile
    int bh  = blockIdx.y;            // 0..31 = b*16+h
    int q0  = blockIdx.x * 128;
    size_t base = (size_t)bh * SEQ * RANK;

    float q[32];
    const float4* qv = (const float4*)(g_qr + base + (size_t)(q0 + tid) * RANK);
#pragma unroll
    for (int c = 0; c < 8; c++) {
        float4 t4 = qv[c];
        q[c*4] = t4.x; q[c*4+1] = t4.y; q[c*4+2] = t4.z; q[c*4+3] = t4.w;
    }

    float mx = -1e30f, l = 0.f;
    float O[32];
#pragma unroll
    for (int r = 0; r < 32; r++) O[r] = 0.f;
    const float scale = 0.17677669529663687f;  // 1/sqrt(32)

    const float4* Ksrc = (const float4*)(g_kr + base);
    const float4* Vsrc = (const float4*)(g_vr + base);
    float4* kd = (float4*)sK;
    float4* vd = (float4*)sV;

    for (int kt = 0; kt < SEQ / 64; kt++) {
#pragma unroll
        for (int i = 0; i < 4; i++) {
            kd[tid + i * 128] = Ksrc[kt * 512 + tid + i * 128];
            vd[tid + i * 128] = Vsrc[kt * 512 + tid + i * 128];
        }
        __syncthreads();

        float s[64];
#pragma unroll
        for (int j = 0; j < 64; j++) {
            const float4* kv = (const float4*)(sK + j * 32);
            float a = 0.f;
#pragma unroll
            for (int c = 0; c < 8; c++) {
                float4 k4 = kv[c];
                a += q[c*4] * k4.x + q[c*4+1] * k4.y + q[c*4+2] * k4.z + q[c*4+3] * k4.w;
            }
            s[j] = a * scale;
        }
        float mt = mx;
#pragma unroll
        for (int j = 0; j < 64; j++) mt = fmaxf(mt, s[j]);
        float corr = __expf(mx - mt);
        mx = mt;
        l *= corr;
#pragma unroll
        for (int r = 0; r < 32; r++) O[r] *= corr;
#pragma unroll
        for (int j = 0; j < 64; j++) {
            float p = __expf(s[j] - mx);
            l += p;
            const float4* vv = (const float4*)(sV + j * 32);
#pragma unroll
            for (int c = 0; c < 8; c++) {
                float4 v4 = vv[c];
                O[c*4]   += p * v4.x;
                O[c*4+1] += p * v4.y;
                O[c*4+2] += p * v4.z;
                O[c*4+3] += p * v4.w;
            }
        }
        __syncthreads();
    }

    float inv = 1.f / l;
    int b = bh >> 4, h = bh & 15;
    float* yp = g_yr + ((size_t)(b * SEQ) + q0 + tid) * K_FOLD + h * RANK;
#pragma unroll
    for (int c = 0; c < 8; c++)
        ((float4*)yp)[c] = make_float4(O[c*4] * inv, O[c*4+1] * inv,
                                       O[c*4+2] * inv, O[c*4+3] * inv);
}

// ---------------- launch --------------------------------------------------
extern "C" void kernel_launch(void* const* d_in, const int* in_sizes, int n_in,
                              void* d_out, int out_size) {
    const float* x     = (const float*)d_in[0];
    const float* Wq    = (const float*)d_in[1];
    const float* Wk    = (const float*)d_in[2];
    const float* Wv    = (const float*)d_in[3];
    const float* Wo    = (const float*)d_in[4];
    const float* Wdown = (const float*)d_in[5];
    const float* Wup   = (const float*)d_in[6];
    float* out = (float*)d_out;

    void *pA, *pBo, *pYr;
    cudaGetSymbolAddress(&pA,  g_Aqkv);
    cudaGetSymbolAddress(&pBo, g_Bo);
    cudaGetSymbolAddress(&pYr, g_yr);

    fold_qkv<<<dim3(D_MODEL/128, N_HEADS, 3), 128>>>(Wq, Wk, Wv, Wdown);
    fold_out<<<dim3(D_MODEL/128, N_HEADS), 128>>>(Wo, Wup);

    // q_r/k_r/v_r = x @ A_qkv (scatter epilogue)
    gemm_kernel<1><<<dim3(N_QKV/128, M_TOT/128), 256>>>(
        x, (const float*)pA, nullptr, M_TOT, N_QKV, D_MODEL);

    // rank-space flash attention -> g_yr [4096, 512]
    attn_kernel<<<dim3(SEQ/128, BATCH*N_HEADS), 128>>>();

    // out = y_r @ B_o
    gemm_kernel<0><<<dim3(D_MODEL/128, M_TOT/128), 256>>>(
        (const float*)pYr, (const float*)pBo, out, M_TOT, D_MODEL, K_FOLD);
}

// round 3
// speedup vs baseline: 1.3553x; 1.3553x over previous
#include <cuda_runtime.h>
#include <cstdint>
#include <cstddef>

#define D_MODEL 2048
#define N_HEADS 16
#define D_HEAD  128
#define RANK    32
#define BATCH   2
#define SEQ     2048
#define M_TOT   (BATCH*SEQ)        // 4096
#define N_QKV   (3*N_HEADS*RANK)   // 1536
#define K_FOLD  (N_HEADS*RANK)     // 512

// ---------------- device scratch (no allocations allowed) ----------------
__device__ float g_Bqkv[(size_t)N_QKV * D_MODEL];   // [1536][2048]  (N,K) K-major
__device__ float g_Bo[(size_t)D_MODEL * K_FOLD];    // [2048][512]   (N,K) K-major
__device__ float g_xc[(size_t)M_TOT * D_MODEL];     // tf32-rounded x
__device__ float g_qr[(size_t)BATCH * N_HEADS * SEQ * RANK];
__device__ float g_kr[(size_t)BATCH * N_HEADS * SEQ * RANK];
__device__ float g_vr[(size_t)BATCH * N_HEADS * SEQ * RANK];
__device__ float g_yr[(size_t)M_TOT * K_FOLD];      // [4096][512]

// ---------------- helpers -------------------------------------------------
__device__ __forceinline__ uint32_t smem_u32(const void* p) {
    uint32_t a;
    asm("{ .reg .u64 t; cvta.to.shared.u64 t, %1; cvt.u32.u64 %0, t; }"
        : "=r"(a) : "l"(p));
    return a;
}

__device__ __forceinline__ float rna_tf32(float v) {
    float o;
    asm("cvt.rna.tf32.f32 %0, %1;" : "=f"(o) : "f"(v));
    return o;
}

__device__ __forceinline__ void cp_async16(uint32_t saddr, const void* gaddr) {
    asm volatile("cp.async.cg.shared.global [%0], [%1], 16;"
                 :: "r"(saddr), "l"(gaddr));
}
#define CP_COMMIT()  asm volatile("cp.async.commit_group;" ::: "memory")
#define CP_WAIT(n)   asm volatile("cp.async.wait_group %0;" :: "n"(n) : "memory")

// tf32 mma m16n8k8 row.col, fp32 accumulate
__device__ __forceinline__ void mma_tf32(float* c, const uint32_t* a, const uint32_t* b) {
    asm volatile(
        "mma.sync.aligned.m16n8k8.row.col.f32.tf32.tf32.f32 "
        "{%0,%1,%2,%3}, {%4,%5,%6,%7}, {%8,%9}, {%0,%1,%2,%3};"
        : "+f"(c[0]), "+f"(c[1]), "+f"(c[2]), "+f"(c[3])
        : "r"(a[0]), "r"(a[1]), "r"(a[2]), "r"(a[3]), "r"(b[0]), "r"(b[1]));
}

// ---------------- fold Wq/Wk/Wv with Wdown (K-major out, tf32-rounded) ----
// B_qkv[w*512+h*32+r][d] = sum_i W_w[h*128+i][d] * Wdown[i][r]
__global__ void fold_qkv(const float* __restrict__ Wq, const float* __restrict__ Wk,
                         const float* __restrict__ Wv, const float* __restrict__ Wdown) {
    __shared__ float sWd[D_HEAD][RANK];
    int tid = threadIdx.x;  // 128
    for (int i = tid; i < D_HEAD*RANK/4; i += 128)
        ((float4*)&sWd[0][0])[i] = ((const float4*)Wdown)[i];
    __syncthreads();

    int h = blockIdx.y;
    int w = blockIdx.z;
    int d = blockIdx.x * 128 + tid;
    const float* W = (w == 0) ? Wq : (w == 1) ? Wk : Wv;
    const float* wp = W + (size_t)h * D_HEAD * D_MODEL + d;

    float acc[RANK];
#pragma unroll
    for (int r = 0; r < RANK; r++) acc[r] = 0.f;
#pragma unroll 4
    for (int i = 0; i < D_HEAD; i++) {
        float wv = wp[(size_t)i * D_MODEL];
#pragma unroll
        for (int r = 0; r < RANK; r++) acc[r] += wv * sWd[i][r];
    }
#pragma unroll
    for (int r = 0; r < RANK; r++)
        g_Bqkv[(size_t)(w * K_FOLD + h * RANK + r) * D_MODEL + d] = rna_tf32(acc[r]);
}

// ---------------- fold Wup with Wo (K-major out [j][h*32+r]) --------------
__global__ void fold_out(const float* __restrict__ Wo, const float* __restrict__ Wup) {
    __shared__ float sWup[RANK][D_HEAD];
    int tid = threadIdx.x;  // 128
    for (int i = tid; i < RANK*D_HEAD/4; i += 128)
        ((float4*)&sWup[0][0])[i] = ((const float4*)Wup)[i];
    __syncthreads();

    int h = blockIdx.y;
    int j = blockIdx.x * 128 + tid;
    const float* wop = Wo + (size_t)j * D_MODEL + h * D_HEAD;

    float acc[RANK];
#pragma unroll
    for (int r = 0; r < RANK; r++) acc[r] = 0.f;
#pragma unroll 2
    for (int i = 0; i < D_HEAD; i += 4) {
        float4 w4 = *(const float4*)(wop + i);
#pragma unroll
        for (int r = 0; r < RANK; r++)
            acc[r] += w4.x * sWup[r][i] + w4.y * sWup[r][i+1]
                    + w4.z * sWup[r][i+2] + w4.w * sWup[r][i+3];
    }
#pragma unroll
    for (int r = 0; r < RANK; r++)
        g_Bo[(size_t)j * K_FOLD + h * RANK + r] = rna_tf32(acc[r]);
}

// ---------------- round x to tf32 -----------------------------------------
__global__ void convert_x(const float4* __restrict__ x, float4* __restrict__ xc) {
    int i = blockIdx.x * 256 + threadIdx.x;
    float4 v = x[i];
    v.x = rna_tf32(v.x); v.y = rna_tf32(v.y);
    v.z = rna_tf32(v.z); v.w = rna_tf32(v.w);
    xc[i] = v;
}

// ---------------- tf32 mma.sync GEMM --------------------------------------
// D[m][n] = sum_k A[m][k]*B[n][k].  A:[M,K], B:[N,K], both row-major (K-major).
// 128x128 block tile, 8 warps of 64x32, K staged 32 wide, cp.async double buffer.
// EPI=0: plain store C[M,N]. EPI=1: scatter into g_qr/g_kr/g_vr.
#define SSTR   36                       // padded floats per smem row
#define ABUF_F (128 * SSTR)             // 4608 floats per tile buffer
#define STAGE_F (2 * ABUF_F)            // A + B one stage
#define SMEM_BYTES (2 * STAGE_F * 4)    // 73728

template <int EPI>
__global__ void __launch_bounds__(256)
gemm_mma(const float* __restrict__ A, const float* __restrict__ B,
         float* __restrict__ C, int N, int K) {
    extern __shared__ float smem[];
    uint32_t sbase = smem_u32(smem);

    int tid = threadIdx.x;
    int lane = tid & 31, wid = tid >> 5;
    int g = lane >> 2, t = lane & 3;
    int wm = (wid >> 2) * 64;       // warp M offset (0 or 64)
    int wn = (wid & 3) * 32;        // warp N offset (0,32,64,96)
    int m0 = blockIdx.y * 128;
    int n0 = blockIdx.x * 128;

    // per-thread load slots: 4 float4 for A, 4 for B
    const float* ga[4];
    const float* gb[4];
    uint32_t sa_off[4], sb_off[4];
#pragma unroll
    for (int i = 0; i < 4; i++) {
        int idx = tid + i * 256;    // 0..1023
        int r  = idx >> 3;          // row 0..127
        int c4 = idx & 7;           // float4 within 32-float row
        ga[i] = A + (size_t)(m0 + r) * K + c4 * 4;
        gb[i] = B + (size_t)(n0 + r) * K + c4 * 4;
        sa_off[i] = (uint32_t)(r * SSTR * 4 + c4 * 16);
        sb_off[i] = (uint32_t)(ABUF_F * 4 + r * SSTR * 4 + c4 * 16);
    }

    float acc[4][4][4];
#pragma unroll
    for (int mt = 0; mt < 4; mt++)
#pragma unroll
        for (int nt = 0; nt < 4; nt++)
#pragma unroll
            for (int e = 0; e < 4; e++) acc[mt][nt][e] = 0.f;

    int nk = K >> 5;

    // prologue: stage chunk 0 into buffer 0
    {
        uint32_t bofs = sbase;
#pragma unroll
        for (int i = 0; i < 4; i++) {
            cp_async16(bofs + sa_off[i], ga[i]);
            cp_async16(bofs + sb_off[i], gb[i]);
        }
        CP_COMMIT();
    }

    for (int kc = 0; kc < nk; kc++) {
        int buf = kc & 1;
        if (kc + 1 < nk) {
            uint32_t bofs = sbase + (buf ^ 1) * (STAGE_F * 4);
            const int ko = (kc + 1) * 32;
#pragma unroll
            for (int i = 0; i < 4; i++) {
                cp_async16(bofs + sa_off[i], ga[i] + ko);
                cp_async16(bofs + sb_off[i], gb[i] + ko);
            }
            CP_COMMIT();
            CP_WAIT(1);
        } else {
            CP_WAIT(0);
        }
        __syncthreads();

        const float* sA = smem + buf * STAGE_F;
        const float* sB = sA + ABUF_F;

#pragma unroll
        for (int ks = 0; ks < 4; ks++) {
            int k0 = ks * 8;
            uint32_t a[4][4], b[4][2];
#pragma unroll
            for (int mt = 0; mt < 4; mt++) {
                const float* p = sA + (wm + mt * 16 + g) * SSTR + k0 + t;
                a[mt][0] = __float_as_uint(p[0]);
                a[mt][1] = __float_as_uint(p[8 * SSTR]);
                a[mt][2] = __float_as_uint(p[4]);
                a[mt][3] = __float_as_uint(p[8 * SSTR + 4]);
            }
#pragma unroll
            for (int nt = 0; nt < 4; nt++) {
                const float* p = sB + (wn + nt * 8 + g) * SSTR + k0 + t;
                b[nt][0] = __float_as_uint(p[0]);
                b[nt][1] = __float_as_uint(p[4]);
            }
#pragma unroll
            for (int mt = 0; mt < 4; mt++)
#pragma unroll
                for (int nt = 0; nt < 4; nt++)
                    mma_tf32(acc[mt][nt], a[mt], b[nt]);
        }
        __syncthreads();
    }

    // epilogue
#pragma unroll
    for (int mt = 0; mt < 4; mt++) {
        int r0 = m0 + wm + mt * 16 + g;
#pragma unroll
        for (int nt = 0; nt < 4; nt++) {
            int cn = n0 + wn + nt * 8 + t * 2;
            if (EPI == 0) {
                *(float2*)(C + (size_t)r0 * N + cn) =
                    make_float2(acc[mt][nt][0], acc[mt][nt][1]);
                *(float2*)(C + (size_t)(r0 + 8) * N + cn) =
                    make_float2(acc[mt][nt][2], acc[mt][nt][3]);
            } else {
                int w = cn >> 9;
                int h = (cn >> 5) & 15;
                int r = cn & 31;
                float* basep = (w == 0) ? g_qr : (w == 1) ? g_kr : g_vr;
                int b0 = r0 >> 11, t0 = r0 & 2047;
                float* p0 = basep + ((size_t)(b0 * N_HEADS + h) * SEQ + t0) * RANK + r;
                *(float2*)p0 = make_float2(acc[mt][nt][0], acc[mt][nt][1]);
                int r1 = r0 + 8;
                int b1 = r1 >> 11, t1 = r1 & 2047;
                float* p1 = basep + ((size_t)(b1 * N_HEADS + h) * SEQ + t1) * RANK + r;
                *(float2*)p1 = make_float2(acc[mt][nt][2], acc[mt][nt][3]);
            }
        }
    }
}

// ---------------- flash attention in rank space (d = 32) -----------------
__global__ __launch_bounds__(128, 3)
void attn_kernel() {
    __shared__ float sK[64 * 32];
    __shared__ float sV[64 * 32];
    int tid = threadIdx.x;           // query row within tile
    int bh  = blockIdx.y;            // b*16+h
    int q0  = blockIdx.x * 128;
    size_t base = (size_t)bh * SEQ * RANK;

    float q[32];
    const float4* qv = (const float4*)(g_qr + base + (size_t)(q0 + tid) * RANK);
#pragma unroll
    for (int c = 0; c < 8; c++) {
        float4 t4 = qv[c];
        q[c*4] = t4.x; q[c*4+1] = t4.y; q[c*4+2] = t4.z; q[c*4+3] = t4.w;
    }

    float mx = -1e30f, l = 0.f;
    float O[32];
#pragma unroll
    for (int r = 0; r < 32; r++) O[r] = 0.f;
    const float scale = 0.17677669529663687f;  // 1/sqrt(32)

    const float4* Ksrc = (const float4*)(g_kr + base);
    const float4* Vsrc = (const float4*)(g_vr + base);
    float4* kd = (float4*)sK;
    float4* vd = (float4*)sV;

    for (int kt = 0; kt < SEQ / 64; kt++) {
#pragma unroll
        for (int i = 0; i < 4; i++) {
            kd[tid + i * 128] = Ksrc[kt * 512 + tid + i * 128];
            vd[tid + i * 128] = Vsrc[kt * 512 + tid + i * 128];
        }
        __syncthreads();

        float s[64];
#pragma unroll
        for (int j = 0; j < 64; j++) {
            const float4* kv = (const float4*)(sK + j * 32);
            float a = 0.f;
#pragma unroll
            for (int c = 0; c < 8; c++) {
                float4 k4 = kv[c];
                a += q[c*4] * k4.x + q[c*4+1] * k4.y + q[c*4+2] * k4.z + q[c*4+3] * k4.w;
            }
            s[j] = a * scale;
        }
        float mt = mx;
#pragma unroll
        for (int j = 0; j < 64; j++) mt = fmaxf(mt, s[j]);
        float corr = __expf(mx - mt);
        mx = mt;
        l *= corr;
#pragma unroll
        for (int r = 0; r < 32; r++) O[r] *= corr;
#pragma unroll
        for (int j = 0; j < 64; j++) {
            float p = __expf(s[j] - mx);
            l += p;
            const float4* vv = (const float4*)(sV + j * 32);
#pragma unroll
            for (int c = 0; c < 8; c++) {
                float4 v4 = vv[c];
                O[c*4]   += p * v4.x;
                O[c*4+1] += p * v4.y;
                O[c*4+2] += p * v4.z;
                O[c*4+3] += p * v4.w;
            }
        }
        __syncthreads();
    }

    float inv = 1.f / l;
    int b = bh >> 4, h = bh & 15;
    float* yp = g_yr + ((size_t)(b * SEQ) + q0 + tid) * K_FOLD + h * RANK;
#pragma unroll
    for (int c = 0; c < 8; c++)
        ((float4*)yp)[c] = make_float4(
            rna_tf32(O[c*4] * inv),   rna_tf32(O[c*4+1] * inv),
            rna_tf32(O[c*4+2] * inv), rna_tf32(O[c*4+3] * inv));
}

// ---------------- launch --------------------------------------------------
extern "C" void kernel_launch(void* const* d_in, const int* in_sizes, int n_in,
                              void* d_out, int out_size) {
    const float* x     = (const float*)d_in[0];
    const float* Wq    = (const float*)d_in[1];
    const float* Wk    = (const float*)d_in[2];
    const float* Wv    = (const float*)d_in[3];
    const float* Wo    = (const float*)d_in[4];
    const float* Wdown = (const float*)d_in[5];
    const float* Wup   = (const float*)d_in[6];
    float* out = (float*)d_out;

    void *pBq, *pBo, *pXc, *pYr;
    cudaGetSymbolAddress(&pBq, g_Bqkv);
    cudaGetSymbolAddress(&pBo, g_Bo);
    cudaGetSymbolAddress(&pXc, g_xc);
    cudaGetSymbolAddress(&pYr, g_yr);

    static bool attr_done = false;
    if (!attr_done) {
        cudaFuncSetAttribute(gemm_mma<0>, cudaFuncAttributeMaxDynamicSharedMemorySize, SMEM_BYTES);
        cudaFuncSetAttribute(gemm_mma<1>, cudaFuncAttributeMaxDynamicSharedMemorySize, SMEM_BYTES);
        attr_done = true;
    }

    convert_x<<<(M_TOT * D_MODEL / 4) / 256, 256>>>((const float4*)x, (float4*)pXc);
    fold_qkv<<<dim3(D_MODEL/128, N_HEADS, 3), 128>>>(Wq, Wk, Wv, Wdown);
    fold_out<<<dim3(D_MODEL/128, N_HEADS), 128>>>(Wo, Wup);

    // q_r/k_r/v_r = x @ A_qkv  (tf32 mma.sync, scatter epilogue)
    gemm_mma<1><<<dim3(N_QKV/128, M_TOT/128), 256, SMEM_BYTES>>>(
        (const float*)pXc, (const float*)pBq, nullptr, N_QKV, D_MODEL);

    // rank-space flash attention -> g_yr [4096, 512]
    attn_kernel<<<dim3(SEQ/128, BATCH*N_HEADS), 128>>>();

    // out = y_r @ B_o  (tf32 mma.sync)
    gemm_mma<0><<<dim3(D_MODEL/128, M_TOT/128), 256, SMEM_BYTES>>>(
        (const float*)pYr, (const float*)pBo, out, D_MODEL, K_FOLD);
}

// round 4
// speedup vs baseline: 3.2621x; 2.4069x over previous
#include <cuda_runtime.h>
#include <cstdint>
#include <cstddef>

#define D_MODEL 2048
#define N_HEADS 16
#define D_HEAD  128
#define RANK    32
#define BATCH   2
#define SEQ     2048
#define M_TOT   (BATCH*SEQ)        // 4096
#define N_QKV   (3*N_HEADS*RANK)   // 1536
#define K_FOLD  (N_HEADS*RANK)     // 512

// ---------------- device scratch (no allocations allowed) ----------------
__device__ float g_Bqkv[(size_t)N_QKV * D_MODEL];   // [1536][2048]  (N,K) K-major
__device__ float g_Bo[(size_t)D_MODEL * K_FOLD];    // [2048][512]   (N,K) K-major
__device__ float g_xc[(size_t)M_TOT * D_MODEL];     // tf32-rounded x
__device__ float g_qr[(size_t)BATCH * N_HEADS * SEQ * RANK];
__device__ float g_kr[(size_t)BATCH * N_HEADS * SEQ * RANK];
__device__ float g_vr[(size_t)BATCH * N_HEADS * SEQ * RANK];
__device__ float g_yr[(size_t)M_TOT * K_FOLD];      // [4096][512]

// ---------------- helpers -------------------------------------------------
__device__ __forceinline__ uint32_t smem_u32(const void* p) {
    uint32_t a;
    asm("{ .reg .u64 t; cvta.to.shared.u64 t, %1; cvt.u32.u64 %0, t; }"
        : "=r"(a) : "l"(p));
    return a;
}

__device__ __forceinline__ float rna_tf32(float v) {
    float o;
    asm("cvt.rna.tf32.f32 %0, %1;" : "=f"(o) : "f"(v));
    return o;
}

__device__ __forceinline__ float tf32_trunc(float v) {
    return __uint_as_float(__float_as_uint(v) & 0xFFFFE000u);
}

__device__ __forceinline__ float ex2f(float x) {
    float y;
    asm("ex2.approx.f32 %0, %1;" : "=f"(y) : "f"(x));
    return y;
}

__device__ __forceinline__ void cp_async16(uint32_t saddr, const void* gaddr) {
    asm volatile("cp.async.cg.shared.global [%0], [%1], 16;"
                 :: "r"(saddr), "l"(gaddr));
}
#define CP_COMMIT()  asm volatile("cp.async.commit_group;" ::: "memory")
#define CP_WAIT(n)   asm volatile("cp.async.wait_group %0;" :: "n"(n) : "memory")

// tf32 mma m16n8k8 row.col, fp32 accumulate
__device__ __forceinline__ void mma_tf32(float* c, const uint32_t* a, const uint32_t* b) {
    asm volatile(
        "mma.sync.aligned.m16n8k8.row.col.f32.tf32.tf32.f32 "
        "{%0,%1,%2,%3}, {%4,%5,%6,%7}, {%8,%9}, {%0,%1,%2,%3};"
        : "+f"(c[0]), "+f"(c[1]), "+f"(c[2]), "+f"(c[3])
        : "r"(a[0]), "r"(a[1]), "r"(a[2]), "r"(a[3]), "r"(b[0]), "r"(b[1]));
}

// ---------------- fold Wq/Wk/Wv with Wdown (K-major out, tf32-rounded) ----
__global__ void fold_qkv(const float* __restrict__ Wq, const float* __restrict__ Wk,
                         const float* __restrict__ Wv, const float* __restrict__ Wdown) {
    __shared__ float sWd[D_HEAD][RANK];
    int tid = threadIdx.x;  // 128
    for (int i = tid; i < D_HEAD*RANK/4; i += 128)
        ((float4*)&sWd[0][0])[i] = ((const float4*)Wdown)[i];
    __syncthreads();

    int h = blockIdx.y;
    int w = blockIdx.z;
    int d = blockIdx.x * 128 + tid;
    const float* W = (w == 0) ? Wq : (w == 1) ? Wk : Wv;
    const float* wp = W + (size_t)h * D_HEAD * D_MODEL + d;

    float acc[RANK];
#pragma unroll
    for (int r = 0; r < RANK; r++) acc[r] = 0.f;
#pragma unroll 4
    for (int i = 0; i < D_HEAD; i++) {
        float wv = wp[(size_t)i * D_MODEL];
#pragma unroll
        for (int r = 0; r < RANK; r++) acc[r] += wv * sWd[i][r];
    }
#pragma unroll
    for (int r = 0; r < RANK; r++)
        g_Bqkv[(size_t)(w * K_FOLD + h * RANK + r) * D_MODEL + d] = rna_tf32(acc[r]);
}

// ---------------- fold Wup with Wo (K-major out [j][h*32+r]) --------------
__global__ void fold_out(const float* __restrict__ Wo, const float* __restrict__ Wup) {
    __shared__ float sWup[RANK][D_HEAD];
    int tid = threadIdx.x;  // 128
    for (int i = tid; i < RANK*D_HEAD/4; i += 128)
        ((float4*)&sWup[0][0])[i] = ((const float4*)Wup)[i];
    __syncthreads();

    int h = blockIdx.y;
    int j = blockIdx.x * 128 + tid;
    const float* wop = Wo + (size_t)j * D_MODEL + h * D_HEAD;

    float acc[RANK];
#pragma unroll
    for (int r = 0; r < RANK; r++) acc[r] = 0.f;
#pragma unroll 2
    for (int i = 0; i < D_HEAD; i += 4) {
        float4 w4 = *(const float4*)(wop + i);
#pragma unroll
        for (int r = 0; r < RANK; r++)
            acc[r] += w4.x * sWup[r][i] + w4.y * sWup[r][i+1]
                    + w4.z * sWup[r][i+2] + w4.w * sWup[r][i+3];
    }
#pragma unroll
    for (int r = 0; r < RANK; r++)
        g_Bo[(size_t)j * K_FOLD + h * RANK + r] = rna_tf32(acc[r]);
}

// ---------------- round x to tf32 -----------------------------------------
__global__ void convert_x(const float4* __restrict__ x, float4* __restrict__ xc) {
    int i = blockIdx.x * 256 + threadIdx.x;
    float4 v = x[i];
    v.x = rna_tf32(v.x); v.y = rna_tf32(v.y);
    v.z = rna_tf32(v.z); v.w = rna_tf32(v.w);
    xc[i] = v;
}

// ---------------- tf32 mma.sync GEMM --------------------------------------
#define SSTR   36
#define ABUF_F (128 * SSTR)
#define STAGE_F (2 * ABUF_F)
#define SMEM_BYTES (2 * STAGE_F * 4)    // 73728

template <int EPI>
__global__ void __launch_bounds__(256)
gemm_mma(const float* __restrict__ A, const float* __restrict__ B,
         float* __restrict__ C, int N, int K) {
    extern __shared__ float smem[];
    uint32_t sbase = smem_u32(smem);

    int tid = threadIdx.x;
    int lane = tid & 31, wid = tid >> 5;
    int g = lane >> 2, t = lane & 3;
    int wm = (wid >> 2) * 64;
    int wn = (wid & 3) * 32;
    int m0 = blockIdx.y * 128;
    int n0 = blockIdx.x * 128;

    const float* ga[4];
    const float* gb[4];
    uint32_t sa_off[4], sb_off[4];
#pragma unroll
    for (int i = 0; i < 4; i++) {
        int idx = tid + i * 256;
        int r  = idx >> 3;
        int c4 = idx & 7;
        ga[i] = A + (size_t)(m0 + r) * K + c4 * 4;
        gb[i] = B + (size_t)(n0 + r) * K + c4 * 4;
        sa_off[i] = (uint32_t)(r * SSTR * 4 + c4 * 16);
        sb_off[i] = (uint32_t)(ABUF_F * 4 + r * SSTR * 4 + c4 * 16);
    }

    float acc[4][4][4];
#pragma unroll
    for (int mt = 0; mt < 4; mt++)
#pragma unroll
        for (int nt = 0; nt < 4; nt++)
#pragma unroll
            for (int e = 0; e < 4; e++) acc[mt][nt][e] = 0.f;

    int nk = K >> 5;

    {
        uint32_t bofs = sbase;
#pragma unroll
        for (int i = 0; i < 4; i++) {
            cp_async16(bofs + sa_off[i], ga[i]);
            cp_async16(bofs + sb_off[i], gb[i]);
        }
        CP_COMMIT();
    }

    for (int kc = 0; kc < nk; kc++) {
        int buf = kc & 1;
        if (kc + 1 < nk) {
            uint32_t bofs = sbase + (buf ^ 1) * (STAGE_F * 4);
            const int ko = (kc + 1) * 32;
#pragma unroll
            for (int i = 0; i < 4; i++) {
                cp_async16(bofs + sa_off[i], ga[i] + ko);
                cp_async16(bofs + sb_off[i], gb[i] + ko);
            }
            CP_COMMIT();
            CP_WAIT(1);
        } else {
            CP_WAIT(0);
        }
        __syncthreads();

        const float* sA = smem + buf * STAGE_F;
        const float* sB = sA + ABUF_F;

#pragma unroll
        for (int ks = 0; ks < 4; ks++) {
            int k0 = ks * 8;
            uint32_t a[4][4], b[4][2];
#pragma unroll
            for (int mt = 0; mt < 4; mt++) {
                const float* p = sA + (wm + mt * 16 + g) * SSTR + k0 + t;
                a[mt][0] = __float_as_uint(p[0]);
                a[mt][1] = __float_as_uint(p[8 * SSTR]);
                a[mt][2] = __float_as_uint(p[4]);
                a[mt][3] = __float_as_uint(p[8 * SSTR + 4]);
            }
#pragma unroll
            for (int nt = 0; nt < 4; nt++) {
                const float* p = sB + (wn + nt * 8 + g) * SSTR + k0 + t;
                b[nt][0] = __float_as_uint(p[0]);
                b[nt][1] = __float_as_uint(p[4]);
            }
#pragma unroll
            for (int mt = 0; mt < 4; mt++)
#pragma unroll
                for (int nt = 0; nt < 4; nt++)
                    mma_tf32(acc[mt][nt], a[mt], b[nt]);
        }
        __syncthreads();
    }

#pragma unroll
    for (int mt = 0; mt < 4; mt++) {
        int r0 = m0 + wm + mt * 16 + g;
#pragma unroll
        for (int nt = 0; nt < 4; nt++) {
            int cn = n0 + wn + nt * 8 + t * 2;
            if (EPI == 0) {
                *(float2*)(C + (size_t)r0 * N + cn) =
                    make_float2(acc[mt][nt][0], acc[mt][nt][1]);
                *(float2*)(C + (size_t)(r0 + 8) * N + cn) =
                    make_float2(acc[mt][nt][2], acc[mt][nt][3]);
            } else {
                // rna-round q/k/v so attention's mma truncation is lossless
                int w = cn >> 9;
                int h = (cn >> 5) & 15;
                int r = cn & 31;
                float* basep = (w == 0) ? g_qr : (w == 1) ? g_kr : g_vr;
                int b0 = r0 >> 11, t0 = r0 & 2047;
                float* p0 = basep + ((size_t)(b0 * N_HEADS + h) * SEQ + t0) * RANK + r;
                *(float2*)p0 = make_float2(rna_tf32(acc[mt][nt][0]), rna_tf32(acc[mt][nt][1]));
                int r1 = r0 + 8;
                int b1 = r1 >> 11, t1 = r1 & 2047;
                float* p1 = basep + ((size_t)(b1 * N_HEADS + h) * SEQ + t1) * RANK + r;
                *(float2*)p1 = make_float2(rna_tf32(acc[mt][nt][2]), rna_tf32(acc[mt][nt][3]));
            }
        }
    }
}

// ---------------- tensor-core flash attention in rank space ---------------
// CTA: 128 q-rows for one (b,h); 4 warps x 32 q-rows; key tiles of 64.
#define TQ   128
#define TK   64
#define NKT  (SEQ/TK)       // 32
#define PSTR 68
#define KSTR 36
#define VSTR 40
#define PWSZ (32*PSTR)      // 2176 floats per warp
#define AOFF_K (4*PWSZ)     // 8704
#define AKSZ (TK*KSTR)      // 2304
#define AVSZ (TK*VSTR)      // 2560
#define ASTG (AKSZ+AVSZ)    // 4864
#define ASMEM_BYTES ((AOFF_K + 2*ASTG)*4)   // 73728

__device__ __forceinline__ void prefetch_kv(uint32_t sbase, int stage,
                                            const float* Kb, const float* Vb,
                                            int kt, int tid) {
    uint32_t off = sbase + (AOFF_K + stage * ASTG) * 4;
    const float* kp = Kb + (size_t)kt * TK * RANK;
    const float* vp = Vb + (size_t)kt * TK * RANK;
#pragma unroll
    for (int j = 0; j < 4; j++) {
        int idx = tid + j * 128;
        int row = idx >> 3, c4 = idx & 7;
        cp_async16(off + (row * KSTR + c4 * 4) * 4, kp + row * RANK + c4 * 4);
        cp_async16(off + (AKSZ + row * VSTR + c4 * 4) * 4, vp + row * RANK + c4 * 4);
    }
    CP_COMMIT();
}

__global__ void __launch_bounds__(128)
attn_mma() {
    extern __shared__ float smem[];
    uint32_t sbase = smem_u32(smem);
    int tid = threadIdx.x;
    int lane = tid & 31, wid = tid >> 5;
    int g = lane >> 2, t = lane & 3;
    int bh = blockIdx.y;
    int q0 = blockIdx.x * TQ;
    int wq = wid * 32;

    const float* Qb = g_qr + ((size_t)bh * SEQ + q0) * RANK;
    const float* Kb = g_kr + (size_t)bh * SEQ * RANK;
    const float* Vb = g_vr + (size_t)bh * SEQ * RANK;

    prefetch_kv(sbase, 0, Kb, Vb, 0, tid);
    prefetch_kv(sbase, 1, Kb, Vb, 1, tid);

    // stage Q (overlays P region; consumed into regs before first P store)
#pragma unroll
    for (int j = 0; j < 8; j++) {
        int idx = tid + j * 128;
        int row = idx >> 3, c4 = idx & 7;
        *(float4*)(smem + row * KSTR + c4 * 4) = *(const float4*)(Qb + row * RANK + c4 * 4);
    }
    __syncthreads();

    uint32_t qf[2][4][4];
#pragma unroll
    for (int mt = 0; mt < 2; mt++)
#pragma unroll
        for (int ks = 0; ks < 4; ks++) {
            const float* p = smem + (wq + mt * 16 + g) * KSTR + ks * 8 + t;
            qf[mt][ks][0] = __float_as_uint(p[0]);
            qf[mt][ks][1] = __float_as_uint(p[8 * KSTR]);
            qf[mt][ks][2] = __float_as_uint(p[4]);
            qf[mt][ks][3] = __float_as_uint(p[8 * KSTR + 4]);
        }
    __syncthreads();

    float m2[4], l[4];
    float oacc[2][4][4];
#pragma unroll
    for (int i = 0; i < 4; i++) { m2[i] = -1e30f; l[i] = 0.f; }
#pragma unroll
    for (int mt = 0; mt < 2; mt++)
#pragma unroll
        for (int nt = 0; nt < 4; nt++)
#pragma unroll
            for (int e = 0; e < 4; e++) oacc[mt][nt][e] = 0.f;

    float* sPw = smem + wid * PWSZ;
    const float SC2 = 0.25503837897544185f;  // (1/sqrt(32)) * log2(e)

    for (int kt = 0; kt < NKT; kt++) {
        if (kt + 1 < NKT) { CP_WAIT(1); } else { CP_WAIT(0); }
        __syncthreads();
        const float* sKb = smem + AOFF_K + (kt & 1) * ASTG;
        const float* sVb = sKb + AKSZ;

        // ---- S = Q K^T (raw, pre-scale) ----
        float sacc[2][8][4];
#pragma unroll
        for (int mt = 0; mt < 2; mt++)
#pragma unroll
            for (int nt = 0; nt < 8; nt++)
#pragma unroll
                for (int e = 0; e < 4; e++) sacc[mt][nt][e] = 0.f;
#pragma unroll
        for (int ks = 0; ks < 4; ks++) {
            uint32_t bk[8][2];
#pragma unroll
            for (int nt = 0; nt < 8; nt++) {
                const float* p = sKb + (nt * 8 + g) * KSTR + ks * 8 + t;
                bk[nt][0] = __float_as_uint(p[0]);
                bk[nt][1] = __float_as_uint(p[4]);
            }
#pragma unroll
            for (int mt = 0; mt < 2; mt++)
#pragma unroll
                for (int nt = 0; nt < 8; nt++)
                    mma_tf32(sacc[mt][nt], qf[mt][ks], bk[nt]);
        }

        // ---- online softmax (base-2 domain) ----
        float mloc[4];
#pragma unroll
        for (int mt = 0; mt < 2; mt++) {
            float a0 = -1e30f, a1 = -1e30f;
#pragma unroll
            for (int nt = 0; nt < 8; nt++) {
                a0 = fmaxf(a0, fmaxf(sacc[mt][nt][0], sacc[mt][nt][1]));
                a1 = fmaxf(a1, fmaxf(sacc[mt][nt][2], sacc[mt][nt][3]));
            }
            mloc[mt * 2] = a0; mloc[mt * 2 + 1] = a1;
        }
#pragma unroll
        for (int i = 0; i < 4; i++) {
            mloc[i] = fmaxf(mloc[i], __shfl_xor_sync(0xffffffffu, mloc[i], 1));
            mloc[i] = fmaxf(mloc[i], __shfl_xor_sync(0xffffffffu, mloc[i], 2));
        }
        float cor[4];
#pragma unroll
        for (int i = 0; i < 4; i++) {
            float mn = fmaxf(m2[i], mloc[i] * SC2);
            cor[i] = ex2f(m2[i] - mn);
            m2[i] = mn;
            l[i] *= cor[i];
        }
#pragma unroll
        for (int mt = 0; mt < 2; mt++)
#pragma unroll
            for (int nt = 0; nt < 4; nt++) {
                oacc[mt][nt][0] *= cor[mt * 2];     oacc[mt][nt][1] *= cor[mt * 2];
                oacc[mt][nt][2] *= cor[mt * 2 + 1]; oacc[mt][nt][3] *= cor[mt * 2 + 1];
            }

        float lad[4] = {0.f, 0.f, 0.f, 0.f};
#pragma unroll
        for (int mt = 0; mt < 2; mt++) {
            int r0 = mt * 16 + g;
#pragma unroll
            for (int nt = 0; nt < 8; nt++) {
                // truncate P to tf32 BEFORE summing l: bias cancels in O/l
                float p0 = tf32_trunc(ex2f(sacc[mt][nt][0] * SC2 - m2[mt * 2]));
                float p1 = tf32_trunc(ex2f(sacc[mt][nt][1] * SC2 - m2[mt * 2]));
                float p2 = tf32_trunc(ex2f(sacc[mt][nt][2] * SC2 - m2[mt * 2 + 1]));
                float p3 = tf32_trunc(ex2f(sacc[mt][nt][3] * SC2 - m2[mt * 2 + 1]));
                lad[mt * 2] += p0 + p1;
                lad[mt * 2 + 1] += p2 + p3;
                *(float2*)(sPw + r0 * PSTR + nt * 8 + 2 * t) = make_float2(p0, p1);
                *(float2*)(sPw + (r0 + 8) * PSTR + nt * 8 + 2 * t) = make_float2(p2, p3);
            }
        }
#pragma unroll
        for (int i = 0; i < 4; i++) {
            lad[i] += __shfl_xor_sync(0xffffffffu, lad[i], 1);
            lad[i] += __shfl_xor_sync(0xffffffffu, lad[i], 2);
            l[i] += lad[i];
        }
        __syncwarp();

        // ---- O += P V ----
#pragma unroll
        for (int ks = 0; ks < 8; ks++) {
            uint32_t af[2][4], bf[4][2];
#pragma unroll
            for (int mt = 0; mt < 2; mt++) {
                const float* p = sPw + (mt * 16 + g) * PSTR + ks * 8 + t;
                af[mt][0] = __float_as_uint(p[0]);
                af[mt][1] = __float_as_uint(p[8 * PSTR]);
                af[mt][2] = __float_as_uint(p[4]);
                af[mt][3] = __float_as_uint(p[8 * PSTR + 4]);
            }
#pragma unroll
            for (int nt = 0; nt < 4; nt++) {
                const float* p = sVb + (ks * 8 + t) * VSTR + nt * 8 + g;
                bf[nt][0] = __float_as_uint(p[0]);
                bf[nt][1] = __float_as_uint(p[4 * VSTR]);
            }
#pragma unroll
            for (int mt = 0; mt < 2; mt++)
#pragma unroll
                for (int nt = 0; nt < 4; nt++)
                    mma_tf32(oacc[mt][nt], af[mt], bf[nt]);
        }
        __syncthreads();
        if (kt + 2 < NKT) prefetch_kv(sbase, kt & 1, Kb, Vb, kt + 2, tid);
    }

    // ---- epilogue: normalize, rna-round (feeds GEMM2 mma), store ----
    int b = bh >> 4, h = bh & 15;
#pragma unroll
    for (int mt = 0; mt < 2; mt++)
#pragma unroll
        for (int lh = 0; lh < 2; lh++) {
            int row = q0 + wq + mt * 16 + g + lh * 8;
            float inv = 1.f / l[mt * 2 + lh];
            float* yp = g_yr + ((size_t)(b * SEQ) + row) * K_FOLD + h * RANK;
#pragma unroll
            for (int nt = 0; nt < 4; nt++)
                *(float2*)(yp + nt * 8 + 2 * t) = make_float2(
                    rna_tf32(oacc[mt][nt][lh * 2] * inv),
                    rna_tf32(oacc[mt][nt][lh * 2 + 1] * inv));
        }
}

// ---------------- launch --------------------------------------------------
extern "C" void kernel_launch(void* const* d_in, const int* in_sizes, int n_in,
                              void* d_out, int out_size) {
    const float* x     = (const float*)d_in[0];
    const float* Wq    = (const float*)d_in[1];
    const float* Wk    = (const float*)d_in[2];
    const float* Wv    = (const float*)d_in[3];
    const float* Wo    = (const float*)d_in[4];
    const float* Wdown = (const float*)d_in[5];
    const float* Wup   = (const float*)d_in[6];
    float* out = (float*)d_out;

    void *pBq, *pBo, *pXc, *pYr;
    cudaGetSymbolAddress(&pBq, g_Bqkv);
    cudaGetSymbolAddress(&pBo, g_Bo);
    cudaGetSymbolAddress(&pXc, g_xc);
    cudaGetSymbolAddress(&pYr, g_yr);

    static bool attr_done = false;
    if (!attr_done) {
        cudaFuncSetAttribute(gemm_mma<0>, cudaFuncAttributeMaxDynamicSharedMemorySize, SMEM_BYTES);
        cudaFuncSetAttribute(gemm_mma<1>, cudaFuncAttributeMaxDynamicSharedMemorySize, SMEM_BYTES);
        cudaFuncSetAttribute(attn_mma,    cudaFuncAttributeMaxDynamicSharedMemorySize, ASMEM_BYTES);
        attr_done = true;
    }

    convert_x<<<(M_TOT * D_MODEL / 4) / 256, 256>>>((const float4*)x, (float4*)pXc);
    fold_qkv<<<dim3(D_MODEL/128, N_HEADS, 3), 128>>>(Wq, Wk, Wv, Wdown);
    fold_out<<<dim3(D_MODEL/128, N_HEADS), 128>>>(Wo, Wup);

    // q_r/k_r/v_r = x @ A_qkv  (tf32 mma.sync, scatter + rna epilogue)
    gemm_mma<1><<<dim3(N_QKV/128, M_TOT/128), 256, SMEM_BYTES>>>(
        (const float*)pXc, (const float*)pBq, nullptr, N_QKV, D_MODEL);

    // rank-space tensor-core flash attention -> g_yr [4096, 512]
    attn_mma<<<dim3(SEQ/TQ, BATCH*N_HEADS), 128, ASMEM_BYTES>>>();

    // out = y_r @ B_o  (tf32 mma.sync)
    gemm_mma<0><<<dim3(D_MODEL/128, M_TOT/128), 256, SMEM_BYTES>>>(
        (const float*)pYr, (const float*)pBo, out, D_MODEL, K_FOLD);
}

// round 5
// speedup vs baseline: 3.6395x; 1.1157x over previous
#include <cuda_runtime.h>
#include <cstdint>
#include <cstddef>

#define D_MODEL 2048
#define N_HEADS 16
#define D_HEAD  128
#define RANK    32
#define BATCH   2
#define SEQ     2048
#define M_TOT   (BATCH*SEQ)        // 4096
#define N_QKV   (3*N_HEADS*RANK)   // 1536
#define K_FOLD  (N_HEADS*RANK)     // 512

// ---------------- device scratch (no allocations allowed) ----------------
__device__ float g_Bqkv[(size_t)N_QKV * D_MODEL];   // [1536][2048]  (N,K) K-major
__device__ float g_Bo[(size_t)D_MODEL * K_FOLD];    // [2048][512]   (N,K) K-major
__device__ float g_xc[(size_t)M_TOT * D_MODEL];     // tf32-rounded x
__device__ float g_qr[(size_t)BATCH * N_HEADS * SEQ * RANK];
__device__ float g_kr[(size_t)BATCH * N_HEADS * SEQ * RANK];
__device__ float g_vr[(size_t)BATCH * N_HEADS * SEQ * RANK];
__device__ float g_yr[(size_t)M_TOT * K_FOLD];      // [4096][512]

// ---------------- helpers -------------------------------------------------
__device__ __forceinline__ uint32_t smem_u32(const void* p) {
    uint32_t a;
    asm("{ .reg .u64 t; cvta.to.shared.u64 t, %1; cvt.u32.u64 %0, t; }"
        : "=r"(a) : "l"(p));
    return a;
}

__device__ __forceinline__ float rna_tf32(float v) {
    float o;
    asm("cvt.rna.tf32.f32 %0, %1;" : "=f"(o) : "f"(v));
    return o;
}

__device__ __forceinline__ float tf32_trunc(float v) {
    return __uint_as_float(__float_as_uint(v) & 0xFFFFE000u);
}

__device__ __forceinline__ float ex2f(float x) {
    float y;
    asm("ex2.approx.f32 %0, %1;" : "=f"(y) : "f"(x));
    return y;
}

__device__ __forceinline__ void cp_async16(uint32_t saddr, const void* gaddr) {
    asm volatile("cp.async.cg.shared.global [%0], [%1], 16;"
                 :: "r"(saddr), "l"(gaddr));
}
#define CP_COMMIT()  asm volatile("cp.async.commit_group;" ::: "memory")
#define CP_WAIT(n)   asm volatile("cp.async.wait_group %0;" :: "n"(n) : "memory")

// tf32 mma m16n8k8 row.col, fp32 accumulate
__device__ __forceinline__ void mma_tf32(float* c, const uint32_t* a, const uint32_t* b) {
    asm volatile(
        "mma.sync.aligned.m16n8k8.row.col.f32.tf32.tf32.f32 "
        "{%0,%1,%2,%3}, {%4,%5,%6,%7}, {%8,%9}, {%0,%1,%2,%3};"
        : "+f"(c[0]), "+f"(c[1]), "+f"(c[2]), "+f"(c[3])
        : "r"(a[0]), "r"(a[1]), "r"(a[2]), "r"(a[3]), "r"(b[0]), "r"(b[1]));
}

// ---------------- fold Wq/Wk/Wv with Wdown (K-major out, tf32-rounded) ----
__global__ void fold_qkv(const float* __restrict__ Wq, const float* __restrict__ Wk,
                         const float* __restrict__ Wv, const float* __restrict__ Wdown) {
    __shared__ float sWd[D_HEAD][RANK];
    int tid = threadIdx.x;  // 128
    for (int i = tid; i < D_HEAD*RANK/4; i += 128)
        ((float4*)&sWd[0][0])[i] = ((const float4*)Wdown)[i];
    __syncthreads();

    int h = blockIdx.y;
    int w = blockIdx.z;
    int d = blockIdx.x * 128 + tid;
    const float* W = (w == 0) ? Wq : (w == 1) ? Wk : Wv;
    const float* wp = W + (size_t)h * D_HEAD * D_MODEL + d;

    float acc[RANK];
#pragma unroll
    for (int r = 0; r < RANK; r++) acc[r] = 0.f;
#pragma unroll 4
    for (int i = 0; i < D_HEAD; i++) {
        float wv = wp[(size_t)i * D_MODEL];
#pragma unroll
        for (int r = 0; r < RANK; r++) acc[r] += wv * sWd[i][r];
    }
#pragma unroll
    for (int r = 0; r < RANK; r++)
        g_Bqkv[(size_t)(w * K_FOLD + h * RANK + r) * D_MODEL + d] = rna_tf32(acc[r]);
}

// ---------------- fold Wup with Wo (K-major out [j][h*32+r]) --------------
__global__ void fold_out(const float* __restrict__ Wo, const float* __restrict__ Wup) {
    __shared__ float sWup[RANK][D_HEAD];
    int tid = threadIdx.x;  // 128
    for (int i = tid; i < RANK*D_HEAD/4; i += 128)
        ((float4*)&sWup[0][0])[i] = ((const float4*)Wup)[i];
    __syncthreads();

    int h = blockIdx.y;
    int j = blockIdx.x * 128 + tid;
    const float* wop = Wo + (size_t)j * D_MODEL + h * D_HEAD;

    float acc[RANK];
#pragma unroll
    for (int r = 0; r < RANK; r++) acc[r] = 0.f;
#pragma unroll 2
    for (int i = 0; i < D_HEAD; i += 4) {
        float4 w4 = *(const float4*)(wop + i);
#pragma unroll
        for (int r = 0; r < RANK; r++)
            acc[r] += w4.x * sWup[r][i] + w4.y * sWup[r][i+1]
                    + w4.z * sWup[r][i+2] + w4.w * sWup[r][i+3];
    }
#pragma unroll
    for (int r = 0; r < RANK; r++)
        g_Bo[(size_t)j * K_FOLD + h * RANK + r] = rna_tf32(acc[r]);
}

// ---------------- round x to tf32 -----------------------------------------
__global__ void convert_x(const float4* __restrict__ x, float4* __restrict__ xc) {
    int i = blockIdx.x * 256 + threadIdx.x;
    float4 v = x[i];
    v.x = rna_tf32(v.x); v.y = rna_tf32(v.y);
    v.z = rna_tf32(v.z); v.w = rna_tf32(v.w);
    xc[i] = v;
}

// ---------------- tf32 mma.sync GEMM --------------------------------------
#define SSTR   36
#define ABUF_F (128 * SSTR)
#define STAGE_F (2 * ABUF_F)
#define SMEM_BYTES (2 * STAGE_F * 4)    // 73728

template <int EPI>
__global__ void __launch_bounds__(256, 2)
gemm_mma(const float* __restrict__ A, const float* __restrict__ B,
         float* __restrict__ C, int N, int K) {
    extern __shared__ float smem[];
    uint32_t sbase = smem_u32(smem);

    int tid = threadIdx.x;
    int lane = tid & 31, wid = tid >> 5;
    int g = lane >> 2, t = lane & 3;
    int wm = (wid >> 2) * 64;
    int wn = (wid & 3) * 32;
    int m0 = blockIdx.y * 128;
    int n0 = blockIdx.x * 128;

    const float* ga[4];
    const float* gb[4];
    uint32_t sa_off[4], sb_off[4];
#pragma unroll
    for (int i = 0; i < 4; i++) {
        int idx = tid + i * 256;
        int r  = idx >> 3;
        int c4 = idx & 7;
        ga[i] = A + (size_t)(m0 + r) * K + c4 * 4;
        gb[i] = B + (size_t)(n0 + r) * K + c4 * 4;
        sa_off[i] = (uint32_t)(r * SSTR * 4 + c4 * 16);
        sb_off[i] = (uint32_t)(ABUF_F * 4 + r * SSTR * 4 + c4 * 16);
    }

    float acc[4][4][4];
#pragma unroll
    for (int mt = 0; mt < 4; mt++)
#pragma unroll
        for (int nt = 0; nt < 4; nt++)
#pragma unroll
            for (int e = 0; e < 4; e++) acc[mt][nt][e] = 0.f;

    int nk = K >> 5;

    {
        uint32_t bofs = sbase;
#pragma unroll
        for (int i = 0; i < 4; i++) {
            cp_async16(bofs + sa_off[i], ga[i]);
            cp_async16(bofs + sb_off[i], gb[i]);
        }
        CP_COMMIT();
    }

    for (int kc = 0; kc < nk; kc++) {
        int buf = kc & 1;
        if (kc + 1 < nk) {
            uint32_t bofs = sbase + (buf ^ 1) * (STAGE_F * 4);
            const int ko = (kc + 1) * 32;
#pragma unroll
            for (int i = 0; i < 4; i++) {
                cp_async16(bofs + sa_off[i], ga[i] + ko);
                cp_async16(bofs + sb_off[i], gb[i] + ko);
            }
            CP_COMMIT();
            CP_WAIT(1);
        } else {
            CP_WAIT(0);
        }
        __syncthreads();

        const float* sA = smem + buf * STAGE_F;
        const float* sB = sA + ABUF_F;

#pragma unroll
        for (int ks = 0; ks < 4; ks++) {
            int k0 = ks * 8;
            uint32_t a[4][4], b[4][2];
#pragma unroll
            for (int mt = 0; mt < 4; mt++) {
                const float* p = sA + (wm + mt * 16 + g) * SSTR + k0 + t;
                a[mt][0] = __float_as_uint(p[0]);
                a[mt][1] = __float_as_uint(p[8 * SSTR]);
                a[mt][2] = __float_as_uint(p[4]);
                a[mt][3] = __float_as_uint(p[8 * SSTR + 4]);
            }
#pragma unroll
            for (int nt = 0; nt < 4; nt++) {
                const float* p = sB + (wn + nt * 8 + g) * SSTR + k0 + t;
                b[nt][0] = __float_as_uint(p[0]);
                b[nt][1] = __float_as_uint(p[4]);
            }
#pragma unroll
            for (int mt = 0; mt < 4; mt++)
#pragma unroll
                for (int nt = 0; nt < 4; nt++)
                    mma_tf32(acc[mt][nt], a[mt], b[nt]);
        }
        __syncthreads();
    }

#pragma unroll
    for (int mt = 0; mt < 4; mt++) {
        int r0 = m0 + wm + mt * 16 + g;
#pragma unroll
        for (int nt = 0; nt < 4; nt++) {
            int cn = n0 + wn + nt * 8 + t * 2;
            if (EPI == 0) {
                *(float2*)(C + (size_t)r0 * N + cn) =
                    make_float2(acc[mt][nt][0], acc[mt][nt][1]);
                *(float2*)(C + (size_t)(r0 + 8) * N + cn) =
                    make_float2(acc[mt][nt][2], acc[mt][nt][3]);
            } else {
                // rna-round q/k/v so attention's mma truncation is lossless
                int w = cn >> 9;
                int h = (cn >> 5) & 15;
                int r = cn & 31;
                float* basep = (w == 0) ? g_qr : (w == 1) ? g_kr : g_vr;
                int b0 = r0 >> 11, t0 = r0 & 2047;
                float* p0 = basep + ((size_t)(b0 * N_HEADS + h) * SEQ + t0) * RANK + r;
                *(float2*)p0 = make_float2(rna_tf32(acc[mt][nt][0]), rna_tf32(acc[mt][nt][1]));
                int r1 = r0 + 8;
                int b1 = r1 >> 11, t1 = r1 & 2047;
                float* p1 = basep + ((size_t)(b1 * N_HEADS + h) * SEQ + t1) * RANK + r;
                *(float2*)p1 = make_float2(rna_tf32(acc[mt][nt][2]), rna_tf32(acc[mt][nt][3]));
            }
        }
    }
}

// ---------------- tensor-core flash attention in rank space ---------------
#define TQ   128
#define TK   64
#define NKT  (SEQ/TK)       // 32
#define PSTR 68
#define KSTR 36
#define VSTR 40
#define PWSZ (32*PSTR)      // 2176 floats per warp
#define AOFF_K (4*PWSZ)     // 8704
#define AKSZ (TK*KSTR)      // 2304
#define AVSZ (TK*VSTR)      // 2560
#define ASTG (AKSZ+AVSZ)    // 4864
#define ASMEM_BYTES ((AOFF_K + 2*ASTG)*4)   // 73728

__device__ __forceinline__ void prefetch_kv(uint32_t sbase, int stage,
                                            const float* Kb, const float* Vb,
                                            int kt, int tid) {
    uint32_t off = sbase + (AOFF_K + stage * ASTG) * 4;
    const float* kp = Kb + (size_t)kt * TK * RANK;
    const float* vp = Vb + (size_t)kt * TK * RANK;
#pragma unroll
    for (int j = 0; j < 4; j++) {
        int idx = tid + j * 128;
        int row = idx >> 3, c4 = idx & 7;
        cp_async16(off + (row * KSTR + c4 * 4) * 4, kp + row * RANK + c4 * 4);
        cp_async16(off + (AKSZ + row * VSTR + c4 * 4) * 4, vp + row * RANK + c4 * 4);
    }
    CP_COMMIT();
}

__global__ void __launch_bounds__(128, 2)
attn_mma() {
    extern __shared__ float smem[];
    uint32_t sbase = smem_u32(smem);
    int tid = threadIdx.x;
    int lane = tid & 31, wid = tid >> 5;
    int g = lane >> 2, t = lane & 3;
    int bh = blockIdx.y;
    int q0 = blockIdx.x * TQ;
    int wq = wid * 32;

    const float* Qb = g_qr + ((size_t)bh * SEQ + q0) * RANK;
    const float* Kb = g_kr + (size_t)bh * SEQ * RANK;
    const float* Vb = g_vr + (size_t)bh * SEQ * RANK;

    prefetch_kv(sbase, 0, Kb, Vb, 0, tid);
    prefetch_kv(sbase, 1, Kb, Vb, 1, tid);

    // stage Q (overlays P region; consumed into regs before first P store)
#pragma unroll
    for (int j = 0; j < 8; j++) {
        int idx = tid + j * 128;
        int row = idx >> 3, c4 = idx & 7;
        *(float4*)(smem + row * KSTR + c4 * 4) = *(const float4*)(Qb + row * RANK + c4 * 4);
    }
    __syncthreads();

    uint32_t qf[2][4][4];
#pragma unroll
    for (int mt = 0; mt < 2; mt++)
#pragma unroll
        for (int ks = 0; ks < 4; ks++) {
            const float* p = smem + (wq + mt * 16 + g) * KSTR + ks * 8 + t;
            qf[mt][ks][0] = __float_as_uint(p[0]);
            qf[mt][ks][1] = __float_as_uint(p[8 * KSTR]);
            qf[mt][ks][2] = __float_as_uint(p[4]);
            qf[mt][ks][3] = __float_as_uint(p[8 * KSTR + 4]);
        }
    __syncthreads();

    float m2[4], l[4];
    float oacc[2][4][4];
#pragma unroll
    for (int i = 0; i < 4; i++) { m2[i] = -1e30f; l[i] = 0.f; }
#pragma unroll
    for (int mt = 0; mt < 2; mt++)
#pragma unroll
        for (int nt = 0; nt < 4; nt++)
#pragma unroll
            for (int e = 0; e < 4; e++) oacc[mt][nt][e] = 0.f;

    float* sPw = smem + wid * PWSZ;
    const float SC2 = 0.25503837897544185f;  // (1/sqrt(32)) * log2(e)

    for (int kt = 0; kt < NKT; kt++) {
        if (kt + 1 < NKT) { CP_WAIT(1); } else { CP_WAIT(0); }
        __syncthreads();
        const float* sKb = smem + AOFF_K + (kt & 1) * ASTG;
        const float* sVb = sKb + AKSZ;

        // ---- S = Q K^T (raw, pre-scale) ----
        float sacc[2][8][4];
#pragma unroll
        for (int mt = 0; mt < 2; mt++)
#pragma unroll
            for (int nt = 0; nt < 8; nt++)
#pragma unroll
                for (int e = 0; e < 4; e++) sacc[mt][nt][e] = 0.f;
#pragma unroll
        for (int ks = 0; ks < 4; ks++) {
            uint32_t bk[8][2];
#pragma unroll
            for (int nt = 0; nt < 8; nt++) {
                const float* p = sKb + (nt * 8 + g) * KSTR + ks * 8 + t;
                bk[nt][0] = __float_as_uint(p[0]);
                bk[nt][1] = __float_as_uint(p[4]);
            }
#pragma unroll
            for (int mt = 0; mt < 2; mt++)
#pragma unroll
                for (int nt = 0; nt < 8; nt++)
                    mma_tf32(sacc[mt][nt], qf[mt][ks], bk[nt]);
        }

        // ---- online softmax (base-2 domain) ----
        float mloc[4];
#pragma unroll
        for (int mt = 0; mt < 2; mt++) {
            float a0 = -1e30f, a1 = -1e30f;
#pragma unroll
            for (int nt = 0; nt < 8; nt++) {
                a0 = fmaxf(a0, fmaxf(sacc[mt][nt][0], sacc[mt][nt][1]));
                a1 = fmaxf(a1, fmaxf(sacc[mt][nt][2], sacc[mt][nt][3]));
            }
            mloc[mt * 2] = a0; mloc[mt * 2 + 1] = a1;
        }
#pragma unroll
        for (int i = 0; i < 4; i++) {
            mloc[i] = fmaxf(mloc[i], __shfl_xor_sync(0xffffffffu, mloc[i], 1));
            mloc[i] = fmaxf(mloc[i], __shfl_xor_sync(0xffffffffu, mloc[i], 2));
        }
        float cor[4];
#pragma unroll
        for (int i = 0; i < 4; i++) {
            float mn = fmaxf(m2[i], mloc[i] * SC2);
            cor[i] = ex2f(m2[i] - mn);
            m2[i] = mn;
            l[i] *= cor[i];
        }
#pragma unroll
        for (int mt = 0; mt < 2; mt++)
#pragma unroll
            for (int nt = 0; nt < 4; nt++) {
                oacc[mt][nt][0] *= cor[mt * 2];     oacc[mt][nt][1] *= cor[mt * 2];
                oacc[mt][nt][2] *= cor[mt * 2 + 1]; oacc[mt][nt][3] *= cor[mt * 2 + 1];
            }

        float lad[4] = {0.f, 0.f, 0.f, 0.f};
#pragma unroll
        for (int mt = 0; mt < 2; mt++) {
            int r0 = mt * 16 + g;
#pragma unroll
            for (int nt = 0; nt < 8; nt++) {
                // truncate P to tf32 BEFORE summing l: bias cancels in O/l
                float p0 = tf32_trunc(ex2f(sacc[mt][nt][0] * SC2 - m2[mt * 2]));
                float p1 = tf32_trunc(ex2f(sacc[mt][nt][1] * SC2 - m2[mt * 2]));
                float p2 = tf32_trunc(ex2f(sacc[mt][nt][2] * SC2 - m2[mt * 2 + 1]));
                float p3 = tf32_trunc(ex2f(sacc[mt][nt][3] * SC2 - m2[mt * 2 + 1]));
                lad[mt * 2] += p0 + p1;
                lad[mt * 2 + 1] += p2 + p3;
                *(float2*)(sPw + r0 * PSTR + nt * 8 + 2 * t) = make_float2(p0, p1);
                *(float2*)(sPw + (r0 + 8) * PSTR + nt * 8 + 2 * t) = make_float2(p2, p3);
            }
        }
#pragma unroll
        for (int i = 0; i < 4; i++) {
            lad[i] += __shfl_xor_sync(0xffffffffu, lad[i], 1);
            lad[i] += __shfl_xor_sync(0xffffffffu, lad[i], 2);
            l[i] += lad[i];
        }
        __syncwarp();

        // ---- O += P V ----
#pragma unroll
        for (int ks = 0; ks < 8; ks++) {
            uint32_t af[2][4], bf[4][2];
#pragma unroll
            for (int mt = 0; mt < 2; mt++) {
                const float* p = sPw + (mt * 16 + g) * PSTR + ks * 8 + t;
                af[mt][0] = __float_as_uint(p[0]);
                af[mt][1] = __float_as_uint(p[8 * PSTR]);
                af[mt][2] = __float_as_uint(p[4]);
                af[mt][3] = __float_as_uint(p[8 * PSTR + 4]);
            }
#pragma unroll
            for (int nt = 0; nt < 4; nt++) {
                const float* p = sVb + (ks * 8 + t) * VSTR + nt * 8 + g;
                bf[nt][0] = __float_as_uint(p[0]);
                bf[nt][1] = __float_as_uint(p[4 * VSTR]);
            }
#pragma unroll
            for (int mt = 0; mt < 2; mt++)
#pragma unroll
                for (int nt = 0; nt < 4; nt++)
                    mma_tf32(oacc[mt][nt], af[mt], bf[nt]);
        }
        __syncthreads();
        if (kt + 2 < NKT) prefetch_kv(sbase, kt & 1, Kb, Vb, kt + 2, tid);
    }

    // ---- epilogue: normalize, rna-round (feeds GEMM2 mma), store ----
    int b = bh >> 4, h = bh & 15;
#pragma unroll
    for (int mt = 0; mt < 2; mt++)
#pragma unroll
        for (int lh = 0; lh < 2; lh++) {
            int row = q0 + wq + mt * 16 + g + lh * 8;
            float inv = 1.f / l[mt * 2 + lh];
            float* yp = g_yr + ((size_t)(b * SEQ) + row) * K_FOLD + h * RANK;
#pragma unroll
            for (int nt = 0; nt < 4; nt++)
                *(float2*)(yp + nt * 8 + 2 * t) = make_float2(
                    rna_tf32(oacc[mt][nt][lh * 2] * inv),
                    rna_tf32(oacc[mt][nt][lh * 2 + 1] * inv));
        }
}

// ---------------- launch --------------------------------------------------
extern "C" void kernel_launch(void* const* d_in, const int* in_sizes, int n_in,
                              void* d_out, int out_size) {
    const float* x     = (const float*)d_in[0];
    const float* Wq    = (const float*)d_in[1];
    const float* Wk    = (const float*)d_in[2];
    const float* Wv    = (const float*)d_in[3];
    const float* Wo    = (const float*)d_in[4];
    const float* Wdown = (const float*)d_in[5];
    const float* Wup   = (const float*)d_in[6];
    float* out = (float*)d_out;

    void *pBq, *pBo, *pXc, *pYr;
    cudaGetSymbolAddress(&pBq, g_Bqkv);
    cudaGetSymbolAddress(&pBo, g_Bo);
    cudaGetSymbolAddress(&pXc, g_xc);
    cudaGetSymbolAddress(&pYr, g_yr);

    static bool attr_done = false;
    if (!attr_done) {
        cudaFuncSetAttribute(gemm_mma<0>, cudaFuncAttributeMaxDynamicSharedMemorySize, SMEM_BYTES);
        cudaFuncSetAttribute(gemm_mma<1>, cudaFuncAttributeMaxDynamicSharedMemorySize, SMEM_BYTES);
        cudaFuncSetAttribute(attn_mma,    cudaFuncAttributeMaxDynamicSharedMemorySize, ASMEM_BYTES);
        attr_done = true;
    }

    convert_x<<<(M_TOT * D_MODEL / 4) / 256, 256>>>((const float4*)x, (float4*)pXc);
    fold_qkv<<<dim3(D_MODEL/128, N_HEADS, 3), 128>>>(Wq, Wk, Wv, Wdown);
    fold_out<<<dim3(D_MODEL/128, N_HEADS), 128>>>(Wo, Wup);

    // q_r/k_r/v_r = x @ A_qkv  (tf32 mma.sync, scatter + rna epilogue)
    gemm_mma<1><<<dim3(N_QKV/128, M_TOT/128), 256, SMEM_BYTES>>>(
        (const float*)pXc, (const float*)pBq, nullptr, N_QKV, D_MODEL);

    // rank-space tensor-core flash attention -> g_yr [4096, 512]
    attn_mma<<<dim3(SEQ/TQ, BATCH*N_HEADS), 128, ASMEM_BYTES>>>();

    // out = y_r @ B_o  (tf32 mma.sync)
    gemm_mma<0><<<dim3(D_MODEL/128, M_TOT/128), 256, SMEM_BYTES>>>(
        (const float*)pYr, (const float*)pBo, out, D_MODEL, K_FOLD);
}